// round 17
// baseline (speedup 1.0000x reference)
#include <cuda_runtime.h>
#include <cuda_bf16.h>
#include <math.h>
#include <stdint.h>

// ---------------------------------------------------------------------------
// V_l_51204600103593: output = real part of V, 8192 x 8192 float32 (256 MiB).
// V = eye(8192) with closed-form 2x2 Hermitian block exp at (123, 4567).
//
// Base = R15 best (41.0 us): fused single pass, STG.256 (st.global.v8.f32),
// grid 148*32 x 256, grid-stride.
//
// R15 observation: steady-state DRAM traffic (209 MB) < bytes written
// (268 MB) -> L2 naturally retains ~60 MB across a replay. R8's .cs split
// failed because .cs is an ignorable hint. This round: WRITE-THROUGH split.
//   * low 96 MiB (written first, fits in ~126 MB L2): normal v8 stores ->
//     dirty lines stay resident; the .wt stream below does not allocate, so
//     they survive to the next replay and become L2 write-hits (no drain).
//   * high 160 MiB: st.global.wt.v8.f32 -> write-through, no L2 dirty state.
// Predicted steady-state DRAM/replay: ~160 MB -> fill ~29-31 us.
// ---------------------------------------------------------------------------

static constexpr long long N_CONST = 8192;
static constexpr long long NN      = N_CONST * N_CONST;   // 67,108,864
static constexpr long long N8      = NN >> 3;             // 8,388,608 32B chunks
static constexpr int       CONN_I  = 123;
static constexpr int       CONN_J  = 4567;
// 32B-chunk granularity: 1024 chunks per row.
static constexpr int KB_I = (CONN_I / 8) * 8;   // 120 (lane offset 3)
static constexpr int KB_J = (CONN_J / 8) * 8;   // 4560 (lane offset 7)

// L2-resident region: 96 MiB of chunks (L2 ~126 MB).
static constexpr long long RES_CHUNKS = (96ll << 20) >> 5;  // 3,145,728

// Closed-form real parts of exp(1j*H) for the 2x2 Hermitian block.
__device__ __forceinline__ void block_exp_real(
    float a, float b, float cr, float ci,
    float& eii_re, float& ejj_re, float& eij_re, float& eji_re) {
    const float t = 0.5f * (a + b);
    const float d = 0.5f * (a - b);
    const float r = sqrtf(d * d + cr * cr + ci * ci);
    const float sinc = (r > 0.f) ? (sinf(r) / r) : 1.f;
    const float cosr = cosf(r);
    float st, ct;
    sincosf(t, &st, &ct);
    eii_re = ct * cosr - st * (sinc * d);
    ejj_re = ct * cosr + st * (sinc * d);
    eij_re = ct * (-sinc * ci) - st * (sinc * cr);
    eji_re = ct * (sinc * ci) - st * (sinc * cr);
}

// 256-bit stores: default (write-back, stays dirty in L2) and write-through.
__device__ __forceinline__ void stg256(float* __restrict__ p,
                                       float v0, float v1, float v2, float v3,
                                       float v4, float v5, float v6, float v7) {
    asm volatile(
        "st.global.v8.f32 [%0], {%1, %2, %3, %4, %5, %6, %7, %8};"
        :: "l"(p),
           "f"(v0), "f"(v1), "f"(v2), "f"(v3),
           "f"(v4), "f"(v5), "f"(v6), "f"(v7)
        : "memory");
}

__device__ __forceinline__ void stg256_wt(float* __restrict__ p,
                                          float v0, float v1, float v2, float v3,
                                          float v4, float v5, float v6, float v7) {
    asm volatile(
        "st.global.wt.v8.f32 [%0], {%1, %2, %3, %4, %5, %6, %7, %8};"
        :: "l"(p),
           "f"(v0), "f"(v1), "f"(v2), "f"(v3),
           "f"(v4), "f"(v5), "f"(v6), "f"(v7)
        : "memory");
}

// ---------------------------------------------------------------------------
// Fused kernel: zero + diagonal + block patch, one pass of STG.256 with a
// residency split at RES_CHUNKS.
// ---------------------------------------------------------------------------
__global__ void fused_fill_kernel(const float* __restrict__ bii,
                                  const float* __restrict__ bjj,
                                  const float* __restrict__ bij_real,
                                  const float* __restrict__ bij_img,
                                  float* __restrict__ out) {
    long long k = (long long)blockIdx.x * blockDim.x + threadIdx.x;
    const long long stride = (long long)gridDim.x * blockDim.x;

    for (; k < N8; k += stride) {
        const int row       = (int)(k >> 10);          // 1024 chunks per row
        const int chunkbase = ((int)k & 1023) << 3;    // first of 8 columns

        float v0 = 0.f, v1 = 0.f, v2 = 0.f, v3 = 0.f;
        float v4 = 0.f, v5 = 0.f, v6 = 0.f, v7 = 0.f;

        // Diagonal element among these 8 columns?
        const unsigned d = (unsigned)(row - chunkbase);
        if (d < 8u) {
            v0 = (d == 0u) ? 1.f : 0.f;
            v1 = (d == 1u) ? 1.f : 0.f;
            v2 = (d == 2u) ? 1.f : 0.f;
            v3 = (d == 3u) ? 1.f : 0.f;
            v4 = (d == 4u) ? 1.f : 0.f;
            v5 = (d == 5u) ? 1.f : 0.f;
            v6 = (d == 6u) ? 1.f : 0.f;
            v7 = (d == 7u) ? 1.f : 0.f;
        }

        // 2x2 block entries (<=2 threads ever take this branch).
        if ((row == CONN_I || row == CONN_J) &&
            (chunkbase == KB_I || chunkbase == KB_J)) {
            float eii, ejj, eij, eji;
            block_exp_real(bii[0], bjj[0], bij_real[0], bij_img[0],
                           eii, ejj, eij, eji);
            if (row == CONN_I) {
                if (chunkbase == KB_I) v3 = eii; else v7 = eij;
            } else {
                if (chunkbase == KB_I) v3 = eji; else v7 = ejj;
            }
        }

        float* p = out + (k << 3);
        if (k < RES_CHUNKS) {
            stg256(p, v0, v1, v2, v3, v4, v5, v6, v7);      // L2-resident
        } else {
            stg256_wt(p, v0, v1, v2, v3, v4, v5, v6, v7);   // write-through
        }
    }
}

// ---------------------------------------------------------------------------
// Fallback path (layout surprise): scalar-safe fill + patches.
// ---------------------------------------------------------------------------
__global__ void fill_zero_scalar(float* __restrict__ out, long long nfloats) {
    long long i = (long long)blockIdx.x * blockDim.x + threadIdx.x;
    const long long stride = (long long)gridDim.x * blockDim.x;
    for (; i < nfloats; i += stride) out[i] = 0.f;
}

__global__ void diag_kernel(float* __restrict__ out) {
    long long i = (long long)blockIdx.x * blockDim.x + threadIdx.x;
    if (i < N_CONST) out[i * (N_CONST + 1)] = 1.f;
}

__global__ void block_kernel(const float* __restrict__ bii,
                             const float* __restrict__ bjj,
                             const float* __restrict__ bij_real,
                             const float* __restrict__ bij_img,
                             float* __restrict__ out) {
    if (threadIdx.x != 0 || blockIdx.x != 0) return;
    float eii, ejj, eij, eji;
    block_exp_real(bii[0], bjj[0], bij_real[0], bij_img[0],
                   eii, ejj, eij, eji);
    out[(long long)CONN_I * N_CONST + CONN_I] = eii;
    out[(long long)CONN_J * N_CONST + CONN_J] = ejj;
    out[(long long)CONN_I * N_CONST + CONN_J] = eij;
    out[(long long)CONN_J * N_CONST + CONN_I] = eji;
}

extern "C" void kernel_launch(void* const* d_in, const int* in_sizes, int n_in,
                              void* d_out, int out_size) {
    if (n_in < 4) return;

    const float* bii      = (const float*)d_in[0];
    const float* bjj      = (const float*)d_in[1];
    const float* bij_real = (const float*)d_in[2];
    const float* bij_img  = (const float*)d_in[3];

    const bool aligned32 = (((uintptr_t)d_out) & 31u) == 0;
    const bool full      = ((long long)out_size == NN);

    if (aligned32 && full) {
        fused_fill_kernel<<<148 * 32, 256>>>(bii, bjj, bij_real, bij_img,
                                             (float*)d_out);
    } else {
        float* outf = (float*)d_out;
        const long long nfloats = (long long)out_size;
        fill_zero_scalar<<<148 * 32, 256>>>(outf, nfloats);
        if (nfloats >= NN) {
            diag_kernel<<<(int)((N_CONST + 255) / 256), 256>>>(outf);
            block_kernel<<<1, 32>>>(bii, bjj, bij_real, bij_img, outf);
        }
    }
}